// round 13
// baseline (speedup 1.0000x reference)
#include <cuda_runtime.h>
#include <cuda_fp16.h>
#include <cuda_bf16.h>

// Inputs (metadata order): data [E*3 f32], t0, tn, beta [1 f32], z0 [N*2 f32]
// Output: scalar f32 = -(sum(log_int) - sum(exp(log_int)))
//
// Math: li = beta - d,  d = |z_i - z_j|^2 in [0, 0.5)
//   sum(li)      = E*beta - sum(d)
//   sum(exp(li)) = exp(beta) * sum(exp(-d))
// exp(-d) = 2^(-d*log2e) via MUFU ex2.approx.
//
// R13 (= R12 fixed): z0 table stored in smem as __half2 (40 KB not 80 KB):
//  - 2 blocks/SM x 1024 thr = 64 warps (occ ~80%) with per-SM fill traffic
//    unchanged vs champion (2x40KB = 80KB)
//  - gathers are 4B LDS.32 (half the bank-conflict degree of float2 LDS.64)
// Half coord error ~1.2e-4 abs -> unbiased over 1M events -> ~1e-5 relative
// on the output (tolerance 1e-3).

__device__ float g_partial[2];        // [0]=sum(d), [1]=sum(exp(-d)); zero-init
__device__ unsigned int g_ticket;     // wraps via atomicInc -> replay-safe

__device__ __forceinline__ float exp_negd(float d) {
    float x = d * -1.4426950408889634f;
    float r;
    asm("ex2.approx.ftz.f32 %0, %1;" : "=f"(r) : "f"(x));
    return r;
}

__device__ __forceinline__ unsigned h2_bits(__half2 h) {
    unsigned u;
    memcpy(&u, &h, 4);
    return u;
}

__global__ void __launch_bounds__(1024, 2)
nll_kernel(const float* __restrict__ data,
           const float* __restrict__ beta,
           const float* __restrict__ z0,
           float* __restrict__ out,
           int E, int N)
{
    extern __shared__ __half2 tab[];   // N half2 = 40 KB for N=10000

    // ---- stage z0 into smem as half2 (read float4 = 2 points per iter) ----
    {
        const float4* z4 = (const float4*)z0;
        int npair = N >> 1;                       // pairs of points
        for (int k = threadIdx.x; k < npair; k += blockDim.x) {
            float4 v = z4[k];
            __half2 h0 = __floats2half2_rn(v.x, v.y);
            __half2 h1 = __floats2half2_rn(v.z, v.w);
            // 8B store of two adjacent half2 entries
            *reinterpret_cast<uint2*>(&tab[2 * k]) =
                make_uint2(h2_bits(h0), h2_bits(h1));
        }
        if (N & 1) {                               // odd remainder
            if (threadIdx.x == 0) {
                float2 v = ((const float2*)z0)[N - 1];
                tab[N - 1] = __floats2half2_rn(v.x, v.y);
            }
        }
    }
    __syncthreads();

    float s_d = 0.0f;   // sum of d
    float s_e = 0.0f;   // sum of exp(-d)

    const int T = gridDim.x * blockDim.x;
    const int gtid = blockIdx.x * blockDim.x + threadIdx.x;
    const int nquad = E >> 2;
    const float4* dp = (const float4*)data;   // 3 float4 per 4 events

    for (int q = gtid; q < nquad; q += T) {
        float4 a = dp[3 * q + 0];   // i0 j0 t0 i1
        float4 b = dp[3 * q + 1];   // j1 t1 i2 j2
        float4 c = dp[3 * q + 2];   // t2 i3 j3 t3

        int i0 = __float2int_rz(a.x), j0 = __float2int_rz(a.y);
        int i1 = __float2int_rz(a.w), j1 = __float2int_rz(b.x);
        int i2 = __float2int_rz(b.z), j2 = __float2int_rz(b.w);
        int i3 = __float2int_rz(c.y), j3 = __float2int_rz(c.z);

        float2 zi0 = __half22float2(tab[i0]), zj0 = __half22float2(tab[j0]);
        float2 zi1 = __half22float2(tab[i1]), zj1 = __half22float2(tab[j1]);
        float2 zi2 = __half22float2(tab[i2]), zj2 = __half22float2(tab[j2]);
        float2 zi3 = __half22float2(tab[i3]), zj3 = __half22float2(tab[j3]);

        float dx0 = zi0.x - zj0.x, dy0 = zi0.y - zj0.y;
        float dx1 = zi1.x - zj1.x, dy1 = zi1.y - zj1.y;
        float dx2 = zi2.x - zj2.x, dy2 = zi2.y - zj2.y;
        float dx3 = zi3.x - zj3.x, dy3 = zi3.y - zj3.y;

        float d0 = fmaf(dx0, dx0, dy0 * dy0);
        float d1 = fmaf(dx1, dx1, dy1 * dy1);
        float d2 = fmaf(dx2, dx2, dy2 * dy2);
        float d3 = fmaf(dx3, dx3, dy3 * dy3);

        s_d += (d0 + d1) + (d2 + d3);
        s_e += (exp_negd(d0) + exp_negd(d1)) + (exp_negd(d2) + exp_negd(d3));
    }

    // tail events (E % 4)
    {
        int rbase = nquad << 2;
        int r = E - rbase;
        if (gtid < r) {
            int e = rbase + gtid;
            int i = __float2int_rz(data[3 * e + 0]);
            int j = __float2int_rz(data[3 * e + 1]);
            float2 zi = __half22float2(tab[i]), zj = __half22float2(tab[j]);
            float dx = zi.x - zj.x, dy = zi.y - zj.y;
            float d = fmaf(dx, dx, dy * dy);
            s_d += d;
            s_e += exp_negd(d);
        }
    }

    // ---- warp reduction ----
    #pragma unroll
    for (int o = 16; o > 0; o >>= 1) {
        s_d += __shfl_xor_sync(0xffffffffu, s_d, o);
        s_e += __shfl_xor_sync(0xffffffffu, s_e, o);
    }

    // ---- block reduction ----
    __shared__ float sm_d[32];
    __shared__ float sm_e[32];
    const int lane = threadIdx.x & 31;
    const int warp = threadIdx.x >> 5;
    if (lane == 0) { sm_d[warp] = s_d; sm_e[warp] = s_e; }
    __syncthreads();

    if (warp == 0) {
        const int nwarps = blockDim.x >> 5;
        s_d = (lane < nwarps) ? sm_d[lane] : 0.0f;
        s_e = (lane < nwarps) ? sm_e[lane] : 0.0f;
        #pragma unroll
        for (int o = 16; o > 0; o >>= 1) {
            s_d += __shfl_xor_sync(0xffffffffu, s_d, o);
            s_e += __shfl_xor_sync(0xffffffffu, s_e, o);
        }
        if (lane == 0) {
            atomicAdd(&g_partial[0], s_d);
            atomicAdd(&g_partial[1], s_e);
            __threadfence();
            unsigned t = atomicInc(&g_ticket, gridDim.x - 1);  // wraps
            if (t == gridDim.x - 1) {
                float Sd = atomicExch(&g_partial[0], 0.0f);
                float Se = atomicExch(&g_partial[1], 0.0f);
                float b = beta[0];
                float sl = (float)E * b - Sd;       // sum(log intensities)
                float se = expf(b) * Se;            // sum(exp(log intensities))
                out[0] = se - sl;                   // -(sl - se)
            }
        }
    }
}

extern "C" void kernel_launch(void* const* d_in, const int* in_sizes, int n_in,
                              void* d_out, int out_size)
{
    const float* data = (const float*)d_in[0];
    // d_in[1] = t0, d_in[2] = tn  (unused)
    const float* beta = (const float*)d_in[3];
    const float* z0   = (const float*)d_in[4];
    float* out = (float*)d_out;

    const int E = in_sizes[0] / 3;
    const int N = in_sizes[4] / 2;
    const size_t smem = (size_t)N * sizeof(__half2);   // 40 KB for N=10000

    cudaFuncSetAttribute(nll_kernel,
                         cudaFuncAttributeMaxDynamicSharedMemorySize,
                         (int)smem);

    const int threads = 1024;
    int blocks = 296;                                  // 2 blocks/SM, one wave
    int max_blocks = (E + threads - 1) / threads;
    if (blocks > max_blocks) blocks = max_blocks;

    nll_kernel<<<blocks, threads, smem>>>(data, beta, z0, out, E, N);
}

// round 14
// speedup vs baseline: 1.0030x; 1.0030x over previous
#include <cuda_runtime.h>
#include <cuda_fp16.h>
#include <cuda_bf16.h>

// Inputs (metadata order): data [E*3 f32], t0, tn, beta [1 f32], z0 [N*2 f32]
// Output: scalar f32 = -(sum(log_int) - sum(exp(log_int)))
//
// Math: li = beta - d,  d = |z_i - z_j|^2
//   sum(li)      = E*beta - sum(d)
//   sum(exp(li)) = exp(beta) * sum(exp(-d))
// exp(-d) = 2^(-d*log2e) via MUFU ex2.approx.
//
// R14: coalesced event stream. Each warp loads 96 CONSECUTIVE float4
// (= 128 events) as v0=base[lane], v1=base[lane+32], v2=base[lane+64] —
// 12 L1tex wavefronts per 128 events (minimum) instead of 36 with the old
// 48B-thread-stride layout. (i,j) fields are re-assembled in-register:
// float4 at global index g has field pattern g%3:
//   r0: (i,j,t,i') r1: (j',t',i,j) r2: (t,i,j,t')
// Each thread owns one chunk of each pattern -> 3 complete pairs + 1 pair
// stitched from its r0 chunk's trailing i and the next float4's leading j
// (shfl_down; lane 31's partner is lane 0's v2.x).
// Table: half2 in smem (40 KB), 2 blocks/SM (R13 best-kernel config).

__device__ float g_partial[2];        // [0]=sum(d), [1]=sum(exp(-d)); zero-init
__device__ unsigned int g_ticket;     // wraps via atomicInc -> replay-safe

__device__ __forceinline__ float exp_negd(float d) {
    float x = d * -1.4426950408889634f;
    float r;
    asm("ex2.approx.ftz.f32 %0, %1;" : "=f"(r) : "f"(x));
    return r;
}

__device__ __forceinline__ unsigned h2_bits(__half2 h) {
    unsigned u;
    memcpy(&u, &h, 4);
    return u;
}

__device__ __forceinline__ void acc_pair(const __half2* __restrict__ tab,
                                         float fi, float fj,
                                         float& s_d, float& s_e)
{
    int i = __float2int_rz(fi);
    int j = __float2int_rz(fj);
    float2 zi = __half22float2(tab[i]);
    float2 zj = __half22float2(tab[j]);
    float dx = zi.x - zj.x, dy = zi.y - zj.y;
    float d = fmaf(dx, dx, dy * dy);
    s_d += d;
    s_e += exp_negd(d);
}

__global__ void __launch_bounds__(1024, 2)
nll_kernel(const float* __restrict__ data,
           const float* __restrict__ beta,
           const float* __restrict__ z0,
           float* __restrict__ out,
           int E, int N)
{
    extern __shared__ __half2 tab[];   // N half2 = 40 KB for N=10000

    // ---- stage z0 into smem as half2 ----
    {
        const float4* z4 = (const float4*)z0;
        int npair = N >> 1;
        for (int k = threadIdx.x; k < npair; k += blockDim.x) {
            float4 v = z4[k];
            __half2 h0 = __floats2half2_rn(v.x, v.y);
            __half2 h1 = __floats2half2_rn(v.z, v.w);
            *reinterpret_cast<uint2*>(&tab[2 * k]) =
                make_uint2(h2_bits(h0), h2_bits(h1));
        }
        if ((N & 1) && threadIdx.x == 0) {
            float2 v = ((const float2*)z0)[N - 1];
            tab[N - 1] = __floats2half2_rn(v.x, v.y);
        }
    }
    __syncthreads();

    float s_d = 0.0f;
    float s_e = 0.0f;

    const int lane = threadIdx.x & 31;
    const int wid_g = (blockIdx.x * blockDim.x + threadIdx.x) >> 5;
    const int NW = (gridDim.x * blockDim.x) >> 5;
    const int niter = E >> 7;                 // 128 events per warp-iter
    const float4* dp = (const float4*)data;

    const int r0 = lane % 3;                  // chunk0 pattern for this lane

    for (int it = wid_g; it < niter; it += NW) {
        const float4* base = dp + (size_t)it * 96;
        float4 v0 = base[lane];               // coalesced: 512B contiguous
        float4 v1 = base[32 + lane];
        float4 v2 = base[64 + lane];

        // next float4's leading element, per chunk
        float xn0 = __shfl_down_sync(0xffffffffu, v0.x, 1);
        float xn1 = __shfl_down_sync(0xffffffffu, v1.x, 1);
        float xn2 = __shfl_down_sync(0xffffffffu, v2.x, 1);
        float v2x0 = __shfl_sync(0xffffffffu, v2.x, 0);
        if (lane == 31) xn1 = v2x0;  // lane31's r0 chunk is chunk1; partner = chunk2 lane0

        // pattern per chunk: chunk0 -> r0, chunk1 -> (r0+2)%3, chunk2 -> (r0+1)%3
        // primary pair extraction by pattern:
        //   r==0: (v.x, v.y)   r==1: (v.z, v.w)   r==2: (v.y, v.z)
        {   // chunk0, pattern r0
            float fi = (r0 == 0) ? v0.x : ((r0 == 1) ? v0.z : v0.y);
            float fj = (r0 == 0) ? v0.y : ((r0 == 1) ? v0.w : v0.z);
            acc_pair(tab, fi, fj, s_d, s_e);
        }
        {   // chunk1, pattern (r0+2)%3
            int r = (r0 + 2) % 3;
            float fi = (r == 0) ? v1.x : ((r == 1) ? v1.z : v1.y);
            float fj = (r == 0) ? v1.y : ((r == 1) ? v1.w : v1.z);
            acc_pair(tab, fi, fj, s_d, s_e);
        }
        {   // chunk2, pattern (r0+1)%3
            int r = (r0 + 1) % 3;
            float fi = (r == 0) ? v2.x : ((r == 1) ? v2.z : v2.y);
            float fj = (r == 0) ? v2.y : ((r == 1) ? v2.w : v2.z);
            acc_pair(tab, fi, fj, s_d, s_e);
        }
        {   // stitched pair from this thread's r0-pattern chunk:
            // lane%3==0 -> chunk0, ==1 -> chunk1, ==2 -> chunk2
            float fi = (r0 == 0) ? v0.w : ((r0 == 1) ? v1.w : v2.w);
            float fj = (r0 == 0) ? xn0 : ((r0 == 1) ? xn1 : xn2);
            acc_pair(tab, fi, fj, s_d, s_e);
        }
    }

    // ---- remainder events (E % 128), scalar path ----
    {
        int rbase = niter << 7;
        int rem = E - rbase;
        int gtid = blockIdx.x * blockDim.x + threadIdx.x;
        if (gtid < rem) {
            int e = rbase + gtid;
            acc_pair(tab, data[3 * e + 0], data[3 * e + 1], s_d, s_e);
        }
    }

    // ---- warp reduction ----
    #pragma unroll
    for (int o = 16; o > 0; o >>= 1) {
        s_d += __shfl_xor_sync(0xffffffffu, s_d, o);
        s_e += __shfl_xor_sync(0xffffffffu, s_e, o);
    }

    // ---- block reduction ----
    __shared__ float sm_d[32];
    __shared__ float sm_e[32];
    const int warp = threadIdx.x >> 5;
    if (lane == 0) { sm_d[warp] = s_d; sm_e[warp] = s_e; }
    __syncthreads();

    if (warp == 0) {
        const int nwarps = blockDim.x >> 5;
        s_d = (lane < nwarps) ? sm_d[lane] : 0.0f;
        s_e = (lane < nwarps) ? sm_e[lane] : 0.0f;
        #pragma unroll
        for (int o = 16; o > 0; o >>= 1) {
            s_d += __shfl_xor_sync(0xffffffffu, s_d, o);
            s_e += __shfl_xor_sync(0xffffffffu, s_e, o);
        }
        if (lane == 0) {
            atomicAdd(&g_partial[0], s_d);
            atomicAdd(&g_partial[1], s_e);
            __threadfence();
            unsigned t = atomicInc(&g_ticket, gridDim.x - 1);  // wraps
            if (t == gridDim.x - 1) {
                float Sd = atomicExch(&g_partial[0], 0.0f);
                float Se = atomicExch(&g_partial[1], 0.0f);
                float b = beta[0];
                float sl = (float)E * b - Sd;       // sum(log intensities)
                float se = expf(b) * Se;            // sum(exp(log intensities))
                out[0] = se - sl;                   // -(sl - se)
            }
        }
    }
}

extern "C" void kernel_launch(void* const* d_in, const int* in_sizes, int n_in,
                              void* d_out, int out_size)
{
    const float* data = (const float*)d_in[0];
    // d_in[1] = t0, d_in[2] = tn  (unused)
    const float* beta = (const float*)d_in[3];
    const float* z0   = (const float*)d_in[4];
    float* out = (float*)d_out;

    const int E = in_sizes[0] / 3;
    const int N = in_sizes[4] / 2;
    const size_t smem = (size_t)N * sizeof(__half2);   // 40 KB for N=10000

    cudaFuncSetAttribute(nll_kernel,
                         cudaFuncAttributeMaxDynamicSharedMemorySize,
                         (int)smem);

    const int threads = 1024;
    int blocks = 296;                                  // 2 blocks/SM, one wave
    int max_blocks = (E + threads - 1) / threads;
    if (blocks > max_blocks) blocks = max_blocks;

    nll_kernel<<<blocks, threads, smem>>>(data, beta, z0, out, E, N);
}